// round 4
// baseline (speedup 1.0000x reference)
#include <cuda_runtime.h>

// CRF loss. One 64-thread CTA per batch row; thread j owns output column j.
// Scaled forward algorithm in probability domain:
//   P_{t+1}[j] = (sum_i P_t[i] * E[i][j]) * exp(f_t[j]),  E = exp(trans)
// E column in registers, P ping-pongs in shared (13 LDS.128/step).
// Exact power-of-2 rescaling every step from the exponent of max(P[1..3]).
// Branch-free inner loop: clamped prefetch, unconditional 64-wide store,
// single fused scale multiply. One __syncthreads per step.

constexpr int TT = 50;    // tags
constexpr int LL = 256;   // max length
constexpr int NTH = 64;
constexpr int STARTT = TT - 2;
constexpr int STOPT  = TT - 1;

#define LOG2E 1.4426950408889634f
#define LN2F  0.6931471805599453f

__device__ float    g_partial[1024];
__device__ unsigned g_done = 0;

__device__ __forceinline__ float ex2(float x) {
    float r;
    asm("ex2.approx.ftz.f32 %0, %1;" : "=f"(r) : "f"(x));
    return r;
}

__device__ __forceinline__ float blockSum64(float v, volatile float* red) {
#pragma unroll
    for (int o = 16; o; o >>= 1) v += __shfl_xor_sync(0xffffffffu, v, o);
    if ((threadIdx.x & 31) == 0) red[threadIdx.x >> 5] = v;
    __syncthreads();
    v = red[0] + red[1];
    __syncthreads();
    return v;
}

__global__ void __launch_bounds__(NTH, 1)
crf_kernel(const float* __restrict__ feats, const float* __restrict__ trans,
           const int* __restrict__ tags, const int* __restrict__ mask,
           float* __restrict__ out) {
    __shared__ __align__(16) float Pb[2][64];
    __shared__ float red[2];
    __shared__ int s_len;
    __shared__ unsigned s_rank;

    const int b   = blockIdx.x;
    const int tid = threadIdx.x;
    const int j   = tid;
    const bool jv = (j < TT);
    const int jc  = jv ? j : (TT - 1);

    if (tid == 0) s_len = 0;
    __syncthreads();

    // ---- sequence length (mask is a 0/1 prefix) ----
    {
        const int4* m4 = (const int4*)(mask + (size_t)b * LL);
        int4 v = m4[tid];
        int c = (v.x != 0) + (v.y != 0) + (v.z != 0) + (v.w != 0);
#pragma unroll
        for (int o = 16; o; o >>= 1) c += __shfl_xor_sync(0xffffffffu, c, o);
        if ((tid & 31) == 0) atomicAdd(&s_len, c);
    }

    // ---- E[:,j] = exp(trans[:,j]) in registers (0 for pad threads) ----
    float E[52];
#pragma unroll
    for (int i = 0; i < TT; i++) {
        float e = ex2(trans[i * TT + jc] * LOG2E);
        E[i] = jv ? e : 0.f;
    }
    E[50] = 0.f; E[51] = 0.f;

    const float* fb = feats + (size_t)b * LL * TT;

    // ---- init: part0 = feats[:,0,:] + trans[START,:], offset by s0 ----
    const float s0 = trans[STARTT * TT + 1];
    {
        float p = jv ? ex2((fb[jc] + trans[STARTT * TT + jc] - s0) * LOG2E) : 0.f;
        Pb[0][j] = p;
    }
    const float C2f = s0 * LOG2E;
    int C2k = 0;
    __syncthreads();
    const int len = s_len;

    // ---- distance-2 feats prefetch (clamped, branch-free) ----
    float fc = (len > 1) ? fb[TT + jc] : 0.f;
    float fn = (len > 2) ? fb[2 * TT + jc] : fc;

    float* Pc = Pb[0];
    float* Pn = Pb[1];
    for (int t = 1; t < len; ++t) {
        float ef = ex2(fc * LOG2E);           // off-chain: ready before barrier
        fc = fn;
        int pidx = t + 2 < len ? t + 2 : len - 1;   // IMNMX, no branch
        fn = fb[pidx * TT + jc];

        const float4* p4 = (const float4*)Pc;
        float4 v0 = p4[0];
        // pivot from P[1..3] (real tags, strictly > 0): exact pow-2 rescale
        float m = fmaxf(fmaxf(v0.y, v0.z), v0.w);
        int   k = (__float_as_int(m) >> 23) - 127;
        float sf = __int_as_float((127 - k) << 23) * ef;   // fused scale

        float a0 = v0.x * E[0], a1 = v0.y * E[1];
        float a2 = v0.z * E[2], a3 = v0.w * E[3];
        float b0 = 0.f, b1 = 0.f, b2 = 0.f, b3 = 0.f;
#pragma unroll
        for (int q = 1; q < 13; q += 2) {
            float4 v = p4[q];
            a0 = fmaf(v.x, E[4 * q + 0], a0);
            a1 = fmaf(v.y, E[4 * q + 1], a1);
            a2 = fmaf(v.z, E[4 * q + 2], a2);
            a3 = fmaf(v.w, E[4 * q + 3], a3);
        }
#pragma unroll
        for (int q = 2; q < 13; q += 2) {
            float4 v = p4[q];
            b0 = fmaf(v.x, E[4 * q + 0], b0);
            b1 = fmaf(v.y, E[4 * q + 1], b1);
            b2 = fmaf(v.z, E[4 * q + 2], b2);
            b3 = fmaf(v.w, E[4 * q + 3], b3);
        }
        float acc = ((a0 + b0) + (a1 + b1)) + ((a2 + b2) + (a3 + b3));
        Pn[j] = acc * sf;                      // unconditional 64-wide store
        C2k += k;                              // off-chain
        __syncthreads();
        float* tmp = Pc; Pc = Pn; Pn = tmp;
    }

    // ---- terminal: logsumexp_i(part[i] + trans[i, STOP]) ----
    const float tref = trans[1 * TT + STOPT];
    float s = 0.f;
    if (jv) {
        float w = ex2((trans[jc * TT + STOPT] - tref) * LOG2E);
        s = Pc[j] * w;
    }
    float sumv = blockSum64(s, red);
    float fwd = (log2f(sumv) + C2f + (float)C2k) * LN2F + tref;

    // ---- gold score ----
    const int* tgb = tags + (size_t)b * LL;
    float gl = 0.f;
    for (int t = tid; t < len; t += NTH) {
        int tg = tgb[t];
        int pv = (t == 0) ? STARTT : tgb[t - 1];
        gl += fb[t * TT + tg] + trans[pv * TT + tg];
    }
    float gold = blockSum64(gl, red);

    if (tid == 0) {
        gold += trans[tgb[len - 1] * TT + STOPT];
        g_partial[b] = fwd - gold;
    }

    // ---- fused finalize: last CTA sums all partials (fixed order) ----
    __threadfence();
    if (tid == 0) s_rank = atomicAdd(&g_done, 1u);
    __syncthreads();
    if (s_rank == gridDim.x - 1) {
        const int B = gridDim.x;
        if (tid < 32) {
            float acc = 0.f;
            for (int i = tid; i < B; i += 32) {
                float v;
                asm volatile("ld.global.cg.f32 %0, [%1];" : "=f"(v)
                             : "l"(&g_partial[i]));
                acc += v;
            }
#pragma unroll
            for (int o = 16; o; o >>= 1)
                acc += __shfl_xor_sync(0xffffffffu, acc, o);
            if (tid == 0) {
                *out = acc;
                g_done = 0;   // reset for next graph replay
            }
        }
    }
}

extern "C" void kernel_launch(void* const* d_in, const int* in_sizes, int n_in,
                              void* d_out, int out_size) {
    const float* feats = (const float*)d_in[0];
    const float* trans = (const float*)d_in[1];
    const int*   tags  = (const int*)d_in[2];
    const int*   mask  = (const int*)d_in[3];
    int B = in_sizes[0] / (LL * TT);

    crf_kernel<<<B, NTH>>>(feats, trans, tags, mask, (float*)d_out);
}

// round 6
// speedup vs baseline: 1.0534x; 1.0534x over previous
#include <cuda_runtime.h>

// CRF loss. One 128-thread CTA per batch row. Thread pair (col, r) with
// col = tid>>1, r = tid&1: each thread computes a 28-term half of the
// 50-term dot product sum_i P[i]*E[i][col]; halves combined with one
// shfl_xor. Scaled forward algorithm in probability domain with exact
// power-of-2 rescaling each step (pivot = max P[1..3], broadcast LDS.128).
// P rows padded to 64 floats (cols 50..63 carry exact zeros; E rows >= 50
// are zero so they contribute nothing). One __syncthreads per step.

constexpr int TT = 50;    // tags
constexpr int PW = 64;    // padded P row (64 floats; 50..63 are zero)
constexpr int LL = 256;   // max length
constexpr int NTH = 128;
constexpr int STARTT = TT - 2;
constexpr int STOPT  = TT - 1;

#define LOG2E 1.4426950408889634f
#define LN2F  0.6931471805599453f

__device__ float    g_partial[1024];
__device__ unsigned g_done = 0;

__device__ __forceinline__ float ex2(float x) {
    float r;
    asm("ex2.approx.ftz.f32 %0, %1;" : "=f"(r) : "f"(x));
    return r;
}

__device__ __forceinline__ float blockSum(float v, volatile float* red) {
#pragma unroll
    for (int o = 16; o; o >>= 1) v += __shfl_xor_sync(0xffffffffu, v, o);
    if ((threadIdx.x & 31) == 0) red[threadIdx.x >> 5] = v;
    __syncthreads();
    v = (red[0] + red[1]) + (red[2] + red[3]);
    __syncthreads();
    return v;
}

__global__ void __launch_bounds__(NTH, 1)
crf_kernel(const float* __restrict__ feats, const float* __restrict__ trans,
           const int* __restrict__ tags, const int* __restrict__ mask,
           float* __restrict__ out) {
    __shared__ __align__(16) float Pb[2][PW];
    __shared__ float red[4];
    __shared__ int s_len;
    __shared__ unsigned s_rank;

    const int b   = blockIdx.x;
    const int tid = threadIdx.x;
    const int col = tid >> 1;          // output column 0..63
    const int r   = tid & 1;           // half index
    const bool cv = (col < TT);
    const int cc  = cv ? col : (TT - 1);

    if (tid == 0) s_len = 0;
    __syncthreads();

    // ---- sequence length (mask is a 0/1 prefix) ----
    {
        const int2* m2 = (const int2*)(mask + (size_t)b * LL);
        int2 v = m2[tid];
        int c = (v.x != 0) + (v.y != 0);
#pragma unroll
        for (int o = 16; o; o >>= 1) c += __shfl_xor_sync(0xffffffffu, c, o);
        if ((tid & 31) == 0) atomicAdd(&s_len, c);
    }

    // ---- E half-column in registers: E[i] = exp(trans[r*28+i][col]) ----
    // zero for rows >= TT and for pad columns
    float E[28];
    const int i0 = r * 28;
#pragma unroll
    for (int i = 0; i < 28; i++) {
        int gi = i0 + i;
        float e = 0.f;
        if (gi < TT && cv) e = ex2(trans[gi * TT + cc] * LOG2E);
        E[i] = e;
    }

    const float* fb = feats + (size_t)b * LL * TT;

    // ---- init: part0 = feats[:,0,:] + trans[START,:], offset by s0 ----
    const float s0 = trans[STARTT * TT + 1];
    if (r == 0) {
        float p = cv ? ex2((fb[cc] + trans[STARTT * TT + cc] - s0) * LOG2E) : 0.f;
        Pb[0][col] = p;
        Pb[1][col] = 0.f;   // pre-zero pad columns of the other buffer too
    }
    const float C2f = s0 * LOG2E;
    int C2k = 0;
    __syncthreads();
    const int len = s_len;

    // ---- distance-2 feats prefetch (clamped, branch-free) ----
    float fc = (len > 1) ? fb[TT + cc] : 0.f;
    float fn = (len > 2) ? fb[2 * TT + cc] : fc;

    float* Pc = Pb[0];
    float* Pn = Pb[1];
    for (int t = 1; t < len; ++t) {
        float ef = ex2(fc * LOG2E);                  // off-chain
        fc = fn;
        int pidx = t + 2 < len ? t + 2 : len - 1;    // IMNMX, branch-free
        fn = fb[pidx * TT + cc];

        // pivot (broadcast): P[1..3] are real-tag probs, strictly > 0
        float4 vp = *(const float4*)Pc;
        float m = fmaxf(fmaxf(vp.y, vp.z), vp.w);
        int   k = (__float_as_int(m) >> 23) - 127;
        float sf = __int_as_float((127 - k) << 23) * ef;

        // 28-term half dot product (rows i0 .. i0+27)
        const float4* p4 = (const float4*)(Pc + i0);
        float a0, a1, a2, a3;
        {
            float4 v = p4[0];
            a0 = v.x * E[0]; a1 = v.y * E[1];
            a2 = v.z * E[2]; a3 = v.w * E[3];
        }
#pragma unroll
        for (int q = 1; q < 7; q++) {
            float4 v = p4[q];
            a0 = fmaf(v.x, E[4 * q + 0], a0);
            a1 = fmaf(v.y, E[4 * q + 1], a1);
            a2 = fmaf(v.z, E[4 * q + 2], a2);
            a3 = fmaf(v.w, E[4 * q + 3], a3);
        }
        float half = (a0 + a1) + (a2 + a3);
        float s = half + __shfl_xor_sync(0xffffffffu, half, 1);
        if (r == 0) Pn[col] = s * sf;   // pad cols: E==0 -> s==0 -> exact 0
        C2k += k;                        // off-chain
        __syncthreads();
        float* tmp = Pc; Pc = Pn; Pn = tmp;
    }

    // ---- terminal: logsumexp_i(part[i] + trans[i, STOP]) ----
    const float tref = trans[1 * TT + STOPT];
    float s = 0.f;
    if (cv && r == 0) {
        float w = ex2((trans[cc * TT + STOPT] - tref) * LOG2E);
        s = Pc[col] * w;
    }
    float sumv = blockSum(s, red);
    float fwd = (log2f(sumv) + C2f + (float)C2k) * LN2F + tref;

    // ---- gold score ----
    const int* tgb = tags + (size_t)b * LL;
    float gl = 0.f;
    for (int t = tid; t < len; t += NTH) {
        int tg = tgb[t];
        int pv = (t == 0) ? STARTT : tgb[t - 1];
        gl += fb[t * TT + tg] + trans[pv * TT + tg];
    }
    float gold = blockSum(gl, red);

    if (tid == 0) {
        gold += trans[tgb[len - 1] * TT + STOPT];
        g_partial[b] = fwd - gold;
    }

    // ---- fused finalize: last CTA sums all partials (fixed order) ----
    __threadfence();
    if (tid == 0) s_rank = atomicAdd(&g_done, 1u);
    __syncthreads();
    if (s_rank == gridDim.x - 1) {
        const int B = gridDim.x;
        if (tid < 32) {
            float acc = 0.f;
            for (int i = tid; i < B; i += 32) {
                float v;
                asm volatile("ld.global.cg.f32 %0, [%1];" : "=f"(v)
                             : "l"(&g_partial[i]));
                acc += v;
            }
#pragma unroll
            for (int o = 16; o; o >>= 1)
                acc += __shfl_xor_sync(0xffffffffu, acc, o);
            if (tid == 0) {
                *out = acc;
                g_done = 0;   // reset for next graph replay
            }
        }
    }
}

extern "C" void kernel_launch(void* const* d_in, const int* in_sizes, int n_in,
                              void* d_out, int out_size) {
    const float* feats = (const float*)d_in[0];
    const float* trans = (const float*)d_in[1];
    const int*   tags  = (const int*)d_in[2];
    const int*   mask  = (const int*)d_in[3];
    int B = in_sizes[0] / (LL * TT);

    crf_kernel<<<B, NTH>>>(feats, trans, tags, mask, (float*)d_out);
}

// round 7
// speedup vs baseline: 1.2631x; 1.1991x over previous
#include <cuda_runtime.h>

// CRF loss via BIDIRECTIONAL scaled forward algorithm: the recurrence is
// linear, Z = beta^T (prod M_t) alpha_0, so one 128-thread CTA per batch row
// runs alpha (t = 0..m) in warps 0-1 and beta (t = len-1..m) in warps 2-3
// simultaneously, meeting at m = (len-1)/2:  Z = sum_i alpha_m[i]*beta_m[i].
// Sequential depth halves: ~256 -> ~128 steps.
// Each step: 13 LDS.128 + 50 FMA per thread, exact pow-2 rescale from the
// exponent of max(P[1..3]) (broadcast LDS.128), one __syncthreads.

constexpr int TT = 50;    // tags
constexpr int LL = 256;   // max length
constexpr int NTH = 128;
constexpr int STARTT = TT - 2;
constexpr int STOPT  = TT - 1;

#define LOG2E 1.4426950408889634f
#define LN2F  0.6931471805599453f

__device__ float    g_partial[1024];
__device__ unsigned g_done = 0;

__device__ __forceinline__ float ex2(float x) {
    float r;
    asm("ex2.approx.ftz.f32 %0, %1;" : "=f"(r) : "f"(x));
    return r;
}

__device__ __forceinline__ float blockSum(float v, volatile float* red) {
#pragma unroll
    for (int o = 16; o; o >>= 1) v += __shfl_xor_sync(0xffffffffu, v, o);
    if ((threadIdx.x & 31) == 0) red[threadIdx.x >> 5] = v;
    __syncthreads();
    v = (red[0] + red[1]) + (red[2] + red[3]);
    __syncthreads();
    return v;
}

__global__ void __launch_bounds__(NTH, 1)
crf_kernel(const float* __restrict__ feats, const float* __restrict__ trans,
           const int* __restrict__ tags, const int* __restrict__ mask,
           float* __restrict__ out) {
    __shared__ __align__(16) float Ab[2][64];   // alpha ping-pong
    __shared__ __align__(16) float Bb[2][64];   // beta  ping-pong (ef-folded)
    __shared__ float red[4];
    __shared__ int s_len, s_kf, s_kb;
    __shared__ unsigned s_rank;

    const int b   = blockIdx.x;
    const int tid = threadIdx.x;
    const bool isF = (tid < 64);       // forward group = warps 0-1
    const int g   = tid & 63;          // lane-in-group = state index
    const bool gv = (g < TT);
    const int gc  = gv ? g : (TT - 1);

    if (tid == 0) s_len = 0;
    __syncthreads();

    // ---- sequence length (mask is a 0/1 prefix) ----
    {
        const int2* m2 = (const int2*)(mask + (size_t)b * LL);
        int2 v = m2[tid];
        int c = (v.x != 0) + (v.y != 0);
#pragma unroll
        for (int o = 16; o; o >>= 1) c += __shfl_xor_sync(0xffffffffu, c, o);
        if ((tid & 31) == 0) atomicAdd(&s_len, c);
    }

    // ---- E in registers: forward thread j holds column E[:,j];
    //      backward thread i holds row E[i,:] (contiguous!) ----
    const float* tbase = isF ? (trans + gc) : (trans + gc * TT);
    const int    tstr  = isF ? TT : 1;
    float E[52];
#pragma unroll
    for (int x = 0; x < TT; x++) {
        float e = gv ? ex2(tbase[x * tstr] * LOG2E) : 0.f;
        E[x] = e;
    }
    E[50] = 0.f; E[51] = 0.f;

    const float* fb = feats + (size_t)b * LL * TT;
    const float s0   = trans[STARTT * TT + 1];
    const float tref = trans[1 * TT + STOPT];
    const float C2f  = s0 * LOG2E;

    __syncthreads();
    const int len = s_len;
    const int nf  = (len - 1) >> 1;        // forward steps
    const int nb  = (len - 1) - nf;        // backward steps (>= nf)

    // ---- group inits ----
    if (isF) {
        float p = gv ? ex2((fb[gc] + trans[STARTT * TT + gc] - s0) * LOG2E) : 0.f;
        Ab[0][g] = p;
    } else {
        float w = gv ? ex2((trans[gc * TT + STOPT] - tref) * LOG2E) : 0.f;
        float f = (nb > 0) ? ex2(fb[(len - 1) * TT + gc] * LOG2E) : 1.f;
        Bb[0][g] = gv ? w * f : 0.f;
    }
    int kacc = 0;

    // ---- distance-2 feats prefetch (clamped, branch-free) ----
    int r1 = isF ? 1 : len - 2;
    int r2 = isF ? 2 : len - 3;
    r1 = min(max(r1, 0), len - 1);
    r2 = min(max(r2, 0), len - 1);
    float fc = fb[r1 * TT + gc];
    float fn = fb[r2 * TT + gc];
    __syncthreads();

    float* Pc = isF ? Ab[0] : Bb[0];
    float* Pn = isF ? Ab[1] : Bb[1];
    const int steps_me = isF ? nf : nb;

    for (int s = 1; s <= nb; ++s) {
        if (s <= steps_me) {
            float efv = ex2(fc * LOG2E);
            if (!isF && s == nb) efv = 1.f;   // beta_m excludes ef_m
            fc = fn;
            int rn = isF ? (s + 2) : (len - 3 - s);
            rn = min(max(rn, 0), len - 1);
            fn = fb[rn * TT + gc];

            // pivot: P[1..3] are real-tag values, strictly > 0
            const float4* p4 = (const float4*)Pc;
            float4 v0 = p4[0];
            float m = fmaxf(fmaxf(v0.y, v0.z), v0.w);
            int   k = (__float_as_int(m) >> 23) - 127;
            float sf = __int_as_float((127 - k) << 23) * efv;

            float a0 = v0.x * E[0], a1 = v0.y * E[1];
            float a2 = v0.z * E[2], a3 = v0.w * E[3];
            float b0 = 0.f, b1 = 0.f, b2 = 0.f, b3 = 0.f;
#pragma unroll
            for (int q = 1; q < 13; q += 2) {
                float4 v = p4[q];
                a0 = fmaf(v.x, E[4 * q + 0], a0);
                a1 = fmaf(v.y, E[4 * q + 1], a1);
                a2 = fmaf(v.z, E[4 * q + 2], a2);
                a3 = fmaf(v.w, E[4 * q + 3], a3);
            }
#pragma unroll
            for (int q = 2; q < 13; q += 2) {
                float4 v = p4[q];
                b0 = fmaf(v.x, E[4 * q + 0], b0);
                b1 = fmaf(v.y, E[4 * q + 1], b1);
                b2 = fmaf(v.z, E[4 * q + 2], b2);
                b3 = fmaf(v.w, E[4 * q + 3], b3);
            }
            float acc = ((a0 + b0) + (a1 + b1)) + ((a2 + b2) + (a3 + b3));
            Pn[g] = acc * sf;
            kacc += k;
            float* t = Pc; Pc = Pn; Pn = t;
        }
        __syncthreads();
    }

    // ---- combine at the midpoint: Z = sum_i alpha_m[i] * beta_m[i] ----
    if (tid == 0)  s_kf = kacc;
    if (tid == 64) s_kb = kacc;
    float z = 0.f;
    if (isF && gv) z = Pc[g] * Bb[nb & 1][g];
    float sumv = blockSum(z, red);     // barrier inside makes s_kf/s_kb visible
    float fwd = (log2f(sumv) + C2f + (float)(s_kf + s_kb)) * LN2F + tref;

    // ---- gold score ----
    const int* tgb = tags + (size_t)b * LL;
    float gl = 0.f;
    for (int t = tid; t < len; t += NTH) {
        int tg = tgb[t];
        int pv = (t == 0) ? STARTT : tgb[t - 1];
        gl += fb[t * TT + tg] + trans[pv * TT + tg];
    }
    float gold = blockSum(gl, red);

    if (tid == 0) {
        gold += trans[tgb[len - 1] * TT + STOPT];
        g_partial[b] = fwd - gold;
    }

    // ---- fused finalize: last CTA sums all partials (fixed order) ----
    __threadfence();
    if (tid == 0) s_rank = atomicAdd(&g_done, 1u);
    __syncthreads();
    if (s_rank == gridDim.x - 1) {
        const int B = gridDim.x;
        if (tid < 32) {
            float acc = 0.f;
            for (int i = tid; i < B; i += 32) {
                float v;
                asm volatile("ld.global.cg.f32 %0, [%1];" : "=f"(v)
                             : "l"(&g_partial[i]));
                acc += v;
            }
#pragma unroll
            for (int o = 16; o; o >>= 1)
                acc += __shfl_xor_sync(0xffffffffu, acc, o);
            if (tid == 0) {
                *out = acc;
                g_done = 0;   // reset for next graph replay
            }
        }
    }
}

extern "C" void kernel_launch(void* const* d_in, const int* in_sizes, int n_in,
                              void* d_out, int out_size) {
    const float* feats = (const float*)d_in[0];
    const float* trans = (const float*)d_in[1];
    const int*   tags  = (const int*)d_in[2];
    const int*   mask  = (const int*)d_in[3];
    int B = in_sizes[0] / (LL * TT);

    crf_kernel<<<B, NTH>>>(feats, trans, tags, mask, (float*)d_out);
}

// round 8
// speedup vs baseline: 1.6837x; 1.3330x over previous
#include <cuda_runtime.h>

// CRF loss via BIDIRECTIONAL scaled forward algorithm. One 128-thread CTA
// per batch row: warps 0-1 run alpha forward (t=0..m), warps 2-3 run beta
// backward (t=len-1..m); Z = sum_i alpha_m[i]*beta_m[i]. Each group has its
// own NAMED barrier and its own tight loop (no cross-group coupling, no
// per-iteration branches). Exact pow-2 rescaling each step from the exponent
// of max(P[1..3]). Backward's final step (which must exclude ef_m) is peeled
// out of the loop.

constexpr int TT = 50;    // tags
constexpr int LL = 256;   // max length
constexpr int NTH = 128;
constexpr int STARTT = TT - 2;
constexpr int STOPT  = TT - 1;

#define LOG2E 1.4426950408889634f
#define LN2F  0.6931471805599453f

__device__ float    g_partial[1024];
__device__ unsigned g_done = 0;

__device__ __forceinline__ float ex2(float x) {
    float r;
    asm("ex2.approx.ftz.f32 %0, %1;" : "=f"(r) : "f"(x));
    return r;
}

__device__ __forceinline__ void barg(int id) {    // group-local named barrier
    asm volatile("bar.sync %0, 64;" :: "r"(id));
}

__device__ __forceinline__ float blockSum(float v, volatile float* red) {
#pragma unroll
    for (int o = 16; o; o >>= 1) v += __shfl_xor_sync(0xffffffffu, v, o);
    if ((threadIdx.x & 31) == 0) red[threadIdx.x >> 5] = v;
    __syncthreads();
    v = (red[0] + red[1]) + (red[2] + red[3]);
    __syncthreads();
    return v;
}

__global__ void __launch_bounds__(NTH, 1)
crf_kernel(const float* __restrict__ feats, const float* __restrict__ trans,
           const int* __restrict__ tags, const int* __restrict__ mask,
           float* __restrict__ out) {
    __shared__ __align__(16) float Ab[2][64];   // alpha ping-pong
    __shared__ __align__(16) float Bb[2][64];   // beta  ping-pong
    __shared__ float red[4];
    __shared__ int s_len, s_kf, s_kb;
    __shared__ unsigned s_rank;

    const int b   = blockIdx.x;
    const int tid = threadIdx.x;
    const bool isF = (tid < 64);       // forward group = warps 0-1
    const int g   = tid & 63;          // state index within group
    const bool gv = (g < TT);
    const int gc  = gv ? g : (TT - 1);
    const int bid = isF ? 1 : 2;       // named barrier id per group

    if (tid == 0) s_len = 0;
    __syncthreads();

    // ---- sequence length (mask is a 0/1 prefix) ----
    {
        const int2* m2 = (const int2*)(mask + (size_t)b * LL);
        int2 v = m2[tid];
        int c = (v.x != 0) + (v.y != 0);
#pragma unroll
        for (int o = 16; o; o >>= 1) c += __shfl_xor_sync(0xffffffffu, c, o);
        if ((tid & 31) == 0) atomicAdd(&s_len, c);
    }

    // ---- E in registers: forward thread j holds column E[:,j];
    //      backward thread i holds row E[i,:] ----
    const float* tbase = isF ? (trans + gc) : (trans + gc * TT);
    const int    tstr  = isF ? TT : 1;
    float E[52];
#pragma unroll
    for (int x = 0; x < TT; x++) E[x] = gv ? ex2(tbase[x * tstr] * LOG2E) : 0.f;
    E[50] = 0.f; E[51] = 0.f;

    const float* fb = feats + (size_t)b * LL * TT;
    const float s0   = trans[STARTT * TT + 1];
    const float tref = trans[1 * TT + STOPT];
    const float C2f  = s0 * LOG2E;

    __syncthreads();
    const int len = s_len;
    const int nf  = (len - 1) >> 1;        // forward steps
    const int nb  = (len - 1) - nf;        // backward steps (>= nf)

    // ---- group inits ----
    if (isF) {
        float p = gv ? ex2((fb[gc] + trans[STARTT * TT + gc] - s0) * LOG2E) : 0.f;
        Ab[0][g] = p;
    } else {
        float w = gv ? ex2((trans[gc * TT + STOPT] - tref) * LOG2E) : 0.f;
        float f = (nb > 0) ? ex2(fb[(len - 1) * TT + gc] * LOG2E) : 1.f;
        Bb[0][g] = gv ? w * f : 0.f;
    }
    int kacc = 0;

    // ---- distance-2 feats prefetch (clamped, branch-free) ----
    int r1 = isF ? 1 : len - 2;
    int r2 = isF ? 2 : len - 3;
    r1 = min(max(r1, 0), len - 1);
    r2 = min(max(r2, 0), len - 1);
    float fc = fb[r1 * TT + gc];
    float fn = fb[r2 * TT + gc];

    float* Pc = isF ? Ab[0] : Bb[0];
    float* Pn = isF ? Ab[1] : Bb[1];
    barg(bid);   // group-local: inits visible within group

    // one recurrence step: Pn = (E-matvec of Pc) * 2^-k * efv, then swap
#define CRF_STEP(EFV)                                                     \
    {                                                                     \
        const float4* p4 = (const float4*)Pc;                             \
        float4 v0 = p4[0];                                                \
        float m = fmaxf(fmaxf(v0.y, v0.z), v0.w);                         \
        int   k = (__float_as_int(m) >> 23) - 127;                        \
        float sf = __int_as_float((127 - k) << 23) * (EFV);               \
        float a0 = v0.x * E[0], a1 = v0.y * E[1];                         \
        float a2 = v0.z * E[2], a3 = v0.w * E[3];                         \
        float b0 = 0.f, b1 = 0.f, b2 = 0.f, b3 = 0.f;                     \
        _Pragma("unroll")                                                 \
        for (int q = 1; q < 13; q += 2) {                                 \
            float4 v = p4[q];                                             \
            a0 = fmaf(v.x, E[4 * q + 0], a0);                             \
            a1 = fmaf(v.y, E[4 * q + 1], a1);                             \
            a2 = fmaf(v.z, E[4 * q + 2], a2);                             \
            a3 = fmaf(v.w, E[4 * q + 3], a3);                             \
        }                                                                 \
        _Pragma("unroll")                                                 \
        for (int q = 2; q < 13; q += 2) {                                 \
            float4 v = p4[q];                                             \
            b0 = fmaf(v.x, E[4 * q + 0], b0);                             \
            b1 = fmaf(v.y, E[4 * q + 1], b1);                             \
            b2 = fmaf(v.z, E[4 * q + 2], b2);                             \
            b3 = fmaf(v.w, E[4 * q + 3], b3);                             \
        }                                                                 \
        float acc = ((a0 + b0) + (a1 + b1)) + ((a2 + b2) + (a3 + b3));    \
        Pn[g] = acc * sf;                                                 \
        kacc += k;                                                        \
        barg(bid);                                                        \
        float* _t = Pc; Pc = Pn; Pn = _t;                                 \
    }

    if (isF) {
        for (int s = 1; s <= nf; ++s) {
            float efv = ex2(fc * LOG2E);
            fc = fn;
            int rn = min(s + 2, len - 1);
            fn = fb[rn * TT + gc];
            CRF_STEP(efv);
        }
    } else {
        for (int s = 1; s < nb; ++s) {          // main backward steps
            float efv = ex2(fc * LOG2E);
            fc = fn;
            int rn = max(len - 3 - s, 0);
            fn = fb[rn * TT + gc];
            CRF_STEP(efv);
        }
        if (nb >= 1) {                           // final step: exclude ef_m
            CRF_STEP(1.0f);
        }
    }
#undef CRF_STEP

    // ---- combine at the midpoint: Z = sum_i alpha_m[i] * beta_m[i] ----
    if (tid == 0)  s_kf = kacc;
    if (tid == 64) s_kb = kacc;
    __syncthreads();                       // both groups done, kf/kb visible
    float z = 0.f;
    if (isF && gv) z = Pc[g] * Bb[nb & 1][g];
    float sumv = blockSum(z, red);
    float fwd = (log2f(sumv) + C2f + (float)(s_kf + s_kb)) * LN2F + tref;

    // ---- gold score ----
    const int* tgb = tags + (size_t)b * LL;
    float gl = 0.f;
    for (int t = tid; t < len; t += NTH) {
        int tg = tgb[t];
        int pv = (t == 0) ? STARTT : tgb[t - 1];
        gl += fb[t * TT + tg] + trans[pv * TT + tg];
    }
    float gold = blockSum(gl, red);

    if (tid == 0) {
        gold += trans[tgb[len - 1] * TT + STOPT];
        g_partial[b] = fwd - gold;
    }

    // ---- fused finalize: last CTA sums all partials (fixed order) ----
    __threadfence();
    if (tid == 0) s_rank = atomicAdd(&g_done, 1u);
    __syncthreads();
    if (s_rank == gridDim.x - 1) {
        const int B = gridDim.x;
        if (tid < 32) {
            float acc = 0.f;
            for (int i = tid; i < B; i += 32) {
                float v;
                asm volatile("ld.global.cg.f32 %0, [%1];" : "=f"(v)
                             : "l"(&g_partial[i]));
                acc += v;
            }
#pragma unroll
            for (int o = 16; o; o >>= 1)
                acc += __shfl_xor_sync(0xffffffffu, acc, o);
            if (tid == 0) {
                *out = acc;
                g_done = 0;   // reset for next graph replay
            }
        }
    }
}

extern "C" void kernel_launch(void* const* d_in, const int* in_sizes, int n_in,
                              void* d_out, int out_size) {
    const float* feats = (const float*)d_in[0];
    const float* trans = (const float*)d_in[1];
    const int*   tags  = (const int*)d_in[2];
    const int*   mask  = (const int*)d_in[3];
    int B = in_sizes[0] / (LL * TT);

    crf_kernel<<<B, NTH>>>(feats, trans, tags, mask, (float*)d_out);
}